// round 11
// baseline (speedup 1.0000x reference)
#include <cuda_runtime.h>
#include <cstdint>

#define CC 256
#define BB 1024
typedef unsigned long long ull;

// Duplicated symmetric edge weights: g_W2[j*CC + c] = (w,w), w = w3[e(min,max)], diag 0.
__device__ float2 g_W2[CC * CC];

__global__ void build_W_kernel(const float* __restrict__ w3) {
    int idx = blockIdx.x * blockDim.x + threadIdx.x;
    if (idx >= CC * CC) return;
    int j = idx >> 8;
    int c = idx & 255;
    float v = 0.0f;
    if (j != c) {
        int p = j < c ? j : c;
        int q = j < c ? c : j;
        int e = p * (2 * CC - p - 1) / 2 + (q - p - 1);  // np.triu_indices(CC,1)
        v = w3[e];
    }
    g_W2[idx] = make_float2(v, v);
}

// Round-robin tournament over 8 channel-tiles: rounds 0..6 = perfect matchings
// (every unordered tile-pair exactly once); rounds 7,8 = diagonal tiles.
__constant__ int c_I[9][4] = {
    {7,1,2,3},{7,2,3,4},{7,3,4,5},{7,4,5,6},{7,5,6,0},{7,6,0,1},{7,0,1,2},
    {0,1,2,3},{4,5,6,7}};
__constant__ int c_J[9][4] = {
    {0,6,5,4},{1,0,6,5},{2,1,0,6},{3,2,1,0},{4,3,2,1},{5,4,3,2},{6,5,4,3},
    {0,1,2,3},{4,5,6,7}};

// ---- packed f32x2 helpers (sm_100a) ----
__device__ __forceinline__ ull pk2(float lo, float hi) {
    ull r;
    asm("mov.b64 %0, {%1, %2};" : "=l"(r) : "f"(lo), "f"(hi));
    return r;
}
__device__ __forceinline__ void upk2(ull v, float& lo, float& hi) {
    asm("mov.b64 {%0, %1}, %2;" : "=f"(lo), "=f"(hi) : "l"(v));
}
__device__ __forceinline__ ull add2(ull a, ull b) {
    ull r;
    asm("add.rn.f32x2 %0, %1, %2;" : "=l"(r) : "l"(a), "l"(b));
    return r;
}
__device__ __forceinline__ ull mul2(ull a, ull b) {
    ull r;
    asm("mul.rn.f32x2 %0, %1, %2;" : "=l"(r) : "l"(a), "l"(b));
    return r;
}
__device__ __forceinline__ ull fma2_(ull a, ull b, ull c) {
    ull r;
    asm("fma.rn.f32x2 %0, %1, %2, %3;" : "=l"(r) : "l"(a), "l"(b), "l"(c));
    return r;
}
__device__ __forceinline__ void red_add(float* p, float v) {
    asm volatile("red.global.add.f32 [%0], %1;" :: "l"(p), "f"(v) : "memory");
}

// v(c,j) = u(|d|)*(x_j-x_c)*W[j,c] is antisymmetric; each unordered pair computed once.
// Row sums -> accI; column sums -> two lane-rotating accumulators accJ0/accJ1
// (shfl-by-2 every 2 steps halves the serial fma->shfl chain; accJ1 gets one
// fix-up shfl at the end). Diag tiles use plain row sums (W diag = 0).
__global__ __launch_bounds__(256, 4) void son_main_kernel(
    const float* __restrict__ x, const float* __restrict__ w1,
    const float* __restrict__ w2, float* __restrict__ out)
{
    __shared__ float2 xs[8][CC];        // 16 KB: xs[p][c] = (row 2p, row 2p+1)*w1[c]
    __shared__ ull    Wt[4][32 * 32];   // 32 KB: Wt[k][jy*32+cx] = dup W[J*32+jy][I*32+cx]

    const int tid  = threadIdx.x;
    const int wrp  = tid >> 5;          // row-pair within group (0..7)
    const int cx   = tid & 31;
    const int rg   = blockIdx.x;        // 0..63
    const int rnd  = blockIdx.y;        // 0..8
    const int rowb = rg * 16;

    // Stage x rows (coalesced; channel = tid)
    {
        float w1s = w1[tid];
#pragma unroll
        for (int p = 0; p < 8; p++) {
            float lo = x[(rowb + 2 * p) * CC + tid] * w1s;
            float hi = x[(rowb + 2 * p + 1) * CC + tid] * w1s;
            xs[p][tid] = make_float2(lo, hi);
        }
    }
    // Stage the round's 4 duplicated W tiles (float4 = 2 dup-entries, coalesced)
#pragma unroll
    for (int k = 0; k < 4; k++) {
        int I = c_I[rnd][k], J = c_J[rnd][k];
#pragma unroll
        for (int m = 0; m < 2; m++) {
            int idx = tid + m * 256;            // 0..511 float4 slots (16 per 32-entry row)
            int jy = idx >> 4;
            int q  = idx & 15;
            float4 v = __ldg(reinterpret_cast<const float4*>(
                                 g_W2 + (J * 32 + jy) * CC + I * 32) + q);
            reinterpret_cast<float4*>(&Wt[k][jy * 32])[q] = v;
        }
    }
    __syncthreads();

    const float s0 = 0.505f * w2[0], s1 = 0.505f * w2[1];
    const float s2 = 0.505f * w2[2], s3 = 0.505f * w2[3];
    const ull C0 = pk2(s0, s0), C1 = pk2(s1, s1);
    const ull C2 = pk2(s2, s2), C3 = pk2(s3, s3);
    const float kf = 0.495f / 0.505f;
    const ull K = pk2(kf, kf);

    const ull* xsf = reinterpret_cast<const ull*>(xs) + wrp * CC;
    const bool diag = (rnd >= 7);
    float* outr0 = out + (rowb + 2 * wrp) * CC;
    float* outr1 = outr0 + CC;

    for (int k = 0; k < 4; k++) {
        const int I = c_I[rnd][k], J = c_J[rnd][k];
        const ull nxc = xsf[I * 32 + cx] ^ 0x8000000080000000ULL;
        const ull* xJ = xsf + J * 32;
        const ull* Wb = Wt[k];
        float lo, hi;

        if (!diag) {
            ull accI = 0ULL, accJ0 = 0ULL, accJ1 = 0ULL;
#pragma unroll
            for (int s2i = 0; s2i < 16; s2i++) {
                // even step s = 2*s2i
                {
                    int jy  = (cx + 2 * s2i) & 31;
                    ull xj  = xJ[jy];
                    ull wpk = Wb[jy * 32 + cx];        // LDS.64, dup pair, conflict-free
                    ull d = add2(xj, nxc);
                    ull a = d & 0x7fffffff7fffffffULL;
                    ull t = fma2_(C3, a, C2);
                    t = fma2_(t, a, C1);
                    t = fma2_(t, a, C0);
                    ull u = fma2_(K, t & 0x7fffffff7fffffffULL, t);
                    ull m = mul2(d, wpk);
                    accI  = fma2_(u, m, accI);
                    accJ0 = fma2_(u, m, accJ0);
                }
                // odd step s = 2*s2i+1
                {
                    int jy  = (cx + 2 * s2i + 1) & 31;
                    ull xj  = xJ[jy];
                    ull wpk = Wb[jy * 32 + cx];
                    ull d = add2(xj, nxc);
                    ull a = d & 0x7fffffff7fffffffULL;
                    ull t = fma2_(C3, a, C2);
                    t = fma2_(t, a, C1);
                    t = fma2_(t, a, C0);
                    ull u = fma2_(K, t & 0x7fffffff7fffffffULL, t);
                    ull m = mul2(d, wpk);
                    accI  = fma2_(u, m, accI);
                    accJ1 = fma2_(u, m, accJ1);
                }
                // rotate both column accumulators by 2 (chain depth halved vs by-1 each step)
                accJ0 = __shfl_sync(0xffffffffu, accJ0, (cx + 2) & 31);
                accJ1 = __shfl_sync(0xffffffffu, accJ1, (cx + 2) & 31);
            }
            // accJ1 partials land one lane short; shift them forward by one.
            accJ1 = __shfl_sync(0xffffffffu, accJ1, (cx + 31) & 31);

            upk2(accI, lo, hi);
            red_add(outr0 + I * 32 + cx, lo);
            red_add(outr1 + I * 32 + cx, hi);
            ull negJ = add2(accJ0, accJ1) ^ 0x8000000080000000ULL;  // v(j,c) = -v(c,j)
            upk2(negJ, lo, hi);
            red_add(outr0 + J * 32 + cx, lo);
            red_add(outr1 + J * 32 + cx, hi);
        } else {
            ull accI = 0ULL;
#pragma unroll
            for (int s = 0; s < 32; s++) {
                int jy  = (cx + s) & 31;
                ull xj  = xJ[jy];
                ull wpk = Wb[jy * 32 + cx];
                ull d = add2(xj, nxc);
                ull a = d & 0x7fffffff7fffffffULL;
                ull t = fma2_(C3, a, C2);
                t = fma2_(t, a, C1);
                t = fma2_(t, a, C0);
                ull u = fma2_(K, t & 0x7fffffff7fffffffULL, t);
                accI = fma2_(u, mul2(d, wpk), accI);
            }
            upk2(accI, lo, hi);
            red_add(outr0 + I * 32 + cx, lo);
            red_add(outr1 + I * 32 + cx, hi);
        }
    }
}

extern "C" void kernel_launch(void* const* d_in, const int* in_sizes, int n_in,
                              void* d_out, int out_size) {
    // Identify inputs by element count (robust to ordering):
    // x: 262144, w1: 256, w2: 4, w3: 32640, diff_indices: 8355840 (unused)
    const float* x = nullptr;
    const float* w1 = nullptr;
    const float* w2 = nullptr;
    const float* w3 = nullptr;
    for (int i = 0; i < n_in; i++) {
        switch (in_sizes[i]) {
            case BB * CC:            x  = (const float*)d_in[i]; break;
            case CC:                 w1 = (const float*)d_in[i]; break;
            case 4:                  w2 = (const float*)d_in[i]; break;
            case CC * (CC - 1) / 2:  w3 = (const float*)d_in[i]; break;
            default: break;  // diff_indices not needed
        }
    }

    build_W_kernel<<<(CC * CC + 255) / 256, 256>>>(w3);
    cudaMemsetAsync(d_out, 0, (size_t)out_size * sizeof(float));  // atomics accumulate
    dim3 grid(BB / 16, 9);     // 64 row-groups x 9 rounds = 576 blocks (one wave @ 4/SM)
    son_main_kernel<<<grid, 256>>>(x, w1, w2, (float*)d_out);
}

// round 12
// speedup vs baseline: 1.1277x; 1.1277x over previous
#include <cuda_runtime.h>
#include <cstdint>

#define CC 256
#define BB 1024
typedef unsigned long long ull;

// Round-robin tournament over 8 channel-tiles: rounds 0..6 = perfect matchings
// (every unordered tile-pair exactly once); rounds 7,8 = diagonal tiles.
__constant__ int c_I[9][4] = {
    {7,1,2,3},{7,2,3,4},{7,3,4,5},{7,4,5,6},{7,5,6,0},{7,6,0,1},{7,0,1,2},
    {0,1,2,3},{4,5,6,7}};
__constant__ int c_J[9][4] = {
    {0,6,5,4},{1,0,6,5},{2,1,0,6},{3,2,1,0},{4,3,2,1},{5,4,3,2},{6,5,4,3},
    {0,1,2,3},{4,5,6,7}};

// Pre-ROTATED W tiles: g_Wrot[((rnd*4+k)*1024) + s*32 + cx]
//   = W[J*32 + ((cx+s)&31)][I*32 + cx],  W symmetric from w3, diag 0.
// Main kernel stages these with linear coalesced copies; hot loop addresses
// them with compile-time immediate offsets (zero per-step index ALU).
__device__ float g_Wrot[9 * 4 * 1024];

__global__ void build_Wrot_kernel(const float* __restrict__ w3) {
    int idx = blockIdx.x * blockDim.x + threadIdx.x;
    if (idx >= 9 * 4 * 1024) return;
    int rnd = idx >> 12;
    int rem = idx & 4095;
    int k   = rem >> 10;
    int s   = (rem >> 5) & 31;
    int cx  = rem & 31;
    int I = c_I[rnd][k], J = c_J[rnd][k];
    int c = I * 32 + cx;
    int j = J * 32 + ((cx + s) & 31);
    float v = 0.0f;
    if (j != c) {
        int p = j < c ? j : c;
        int q = j < c ? c : j;
        int e = p * (2 * CC - p - 1) / 2 + (q - p - 1);  // np.triu_indices(CC,1)
        v = w3[e];
    }
    g_Wrot[idx] = v;
}

// ---- packed f32x2 helpers (sm_100a) ----
__device__ __forceinline__ ull pk2(float lo, float hi) {
    ull r;
    asm("mov.b64 %0, {%1, %2};" : "=l"(r) : "f"(lo), "f"(hi));
    return r;
}
__device__ __forceinline__ void upk2(ull v, float& lo, float& hi) {
    asm("mov.b64 {%0, %1}, %2;" : "=f"(lo), "=f"(hi) : "l"(v));
}
__device__ __forceinline__ ull add2(ull a, ull b) {
    ull r;
    asm("add.rn.f32x2 %0, %1, %2;" : "=l"(r) : "l"(a), "l"(b));
    return r;
}
__device__ __forceinline__ ull mul2(ull a, ull b) {
    ull r;
    asm("mul.rn.f32x2 %0, %1, %2;" : "=l"(r) : "l"(a), "l"(b));
    return r;
}
__device__ __forceinline__ ull fma2_(ull a, ull b, ull c) {
    ull r;
    asm("fma.rn.f32x2 %0, %1, %2, %3;" : "=l"(r) : "l"(a), "l"(b), "l"(c));
    return r;
}
__device__ __forceinline__ void red_add(float* p, float v) {
    asm volatile("red.global.add.f32 [%0], %1;" :: "l"(p), "f"(v) : "memory");
}

// v(c,j) = u(|d|)*(x_j-x_c)*W[j,c] is antisymmetric; each unordered pair computed once.
// Row sums -> accI; column sums -> dual lane-rotating accJ0/accJ1 (shfl-by-2 every
// 2 steps; accJ1 fixed up by one forward shfl). W pre-rotated, x duplicated per tile:
// all hot-loop addresses are base-reg + immediate. Diag tiles: row sums only.
__global__ __launch_bounds__(256, 4) void son_main_kernel(
    const float* __restrict__ x, const float* __restrict__ w1,
    const float* __restrict__ w2, float* __restrict__ out)
{
    __shared__ float  Wr[4][1024];     // 16 KB: Wr[k][s*32+cx], pre-rotated
    __shared__ float2 xd[8][8][64];    // 32 KB: xd[p][T][i] = x-pair for ch T*32+(i&31), dup'd

    const int tid  = threadIdx.x;
    const int wrp  = tid >> 5;         // row-pair within group (0..7)
    const int cx   = tid & 31;
    const int rg   = blockIdx.x;       // 0..63
    const int rnd  = blockIdx.y;       // 0..8
    const int rowb = rg * 16;

    // Stage x rows, duplicated within each 32-channel tile (coalesced reads)
    {
        float w1s = w1[tid];
        int T = tid >> 5, ci = tid & 31;
#pragma unroll
        for (int p = 0; p < 8; p++) {
            float lo = x[(rowb + 2 * p) * CC + tid] * w1s;
            float hi = x[(rowb + 2 * p + 1) * CC + tid] * w1s;
            float2 v = make_float2(lo, hi);
            xd[p][T][ci]      = v;
            xd[p][T][ci + 32] = v;
        }
    }
    // Stage the round's 4 rotated W tiles: 1024 float4, linear & coalesced
    {
        const float4* src = reinterpret_cast<const float4*>(g_Wrot + rnd * 4096);
        float4* dst = reinterpret_cast<float4*>(&Wr[0][0]);
#pragma unroll
        for (int m = 0; m < 4; m++)
            dst[tid + m * 256] = __ldg(src + tid + m * 256);
    }
    __syncthreads();

    const float s0 = 0.505f * w2[0], s1 = 0.505f * w2[1];
    const float s2 = 0.505f * w2[2], s3 = 0.505f * w2[3];
    const ull C0 = pk2(s0, s0), C1 = pk2(s1, s1);
    const ull C2 = pk2(s2, s2), C3 = pk2(s3, s3);
    const float kf = 0.495f / 0.505f;
    const ull K = pk2(kf, kf);

    const bool diag = (rnd >= 7);
    float* outr0 = out + (rowb + 2 * wrp) * CC;
    float* outr1 = outr0 + CC;

#pragma unroll 1
    for (int k = 0; k < 4; k++) {
        const int I = c_I[rnd][k], J = c_J[rnd][k];
        const ull nxc = (*reinterpret_cast<const ull*>(&xd[wrp][I][cx])) ^ 0x8000000080000000ULL;
        const ull*   xb = reinterpret_cast<const ull*>(&xd[wrp][J][cx]);  // xb[s]: immediate
        const float* Wb = &Wr[k][cx];                                     // Wb[s*32]: immediate
        float lo, hi;

        if (!diag) {
            ull accI = 0ULL, accJ0 = 0ULL, accJ1 = 0ULL;
#pragma unroll
            for (int s2i = 0; s2i < 16; s2i++) {
                {   // even step s = 2*s2i
                    float w = Wb[(2 * s2i) * 32];
                    ull xj  = xb[2 * s2i];
                    ull wpk = pk2(w, w);
                    ull d = add2(xj, nxc);
                    ull a = d & 0x7fffffff7fffffffULL;
                    ull t = fma2_(C3, a, C2);
                    t = fma2_(t, a, C1);
                    t = fma2_(t, a, C0);
                    ull u = fma2_(K, t & 0x7fffffff7fffffffULL, t);
                    ull m = mul2(d, wpk);
                    accI  = fma2_(u, m, accI);
                    accJ0 = fma2_(u, m, accJ0);
                }
                {   // odd step s = 2*s2i+1
                    float w = Wb[(2 * s2i + 1) * 32];
                    ull xj  = xb[2 * s2i + 1];
                    ull wpk = pk2(w, w);
                    ull d = add2(xj, nxc);
                    ull a = d & 0x7fffffff7fffffffULL;
                    ull t = fma2_(C3, a, C2);
                    t = fma2_(t, a, C1);
                    t = fma2_(t, a, C0);
                    ull u = fma2_(K, t & 0x7fffffff7fffffffULL, t);
                    ull m = mul2(d, wpk);
                    accI  = fma2_(u, m, accI);
                    accJ1 = fma2_(u, m, accJ1);
                }
                accJ0 = __shfl_sync(0xffffffffu, accJ0, (cx + 2) & 31);
                accJ1 = __shfl_sync(0xffffffffu, accJ1, (cx + 2) & 31);
            }
            accJ1 = __shfl_sync(0xffffffffu, accJ1, (cx + 31) & 31);  // one-lane fix-up

            upk2(accI, lo, hi);
            red_add(outr0 + I * 32 + cx, lo);
            red_add(outr1 + I * 32 + cx, hi);
            ull negJ = add2(accJ0, accJ1) ^ 0x8000000080000000ULL;    // v(j,c) = -v(c,j)
            upk2(negJ, lo, hi);
            red_add(outr0 + J * 32 + cx, lo);
            red_add(outr1 + J * 32 + cx, hi);
        } else {
            ull accI = 0ULL;
#pragma unroll
            for (int s = 0; s < 32; s++) {
                float w = Wb[s * 32];
                ull xj  = xb[s];
                ull wpk = pk2(w, w);
                ull d = add2(xj, nxc);
                ull a = d & 0x7fffffff7fffffffULL;
                ull t = fma2_(C3, a, C2);
                t = fma2_(t, a, C1);
                t = fma2_(t, a, C0);
                ull u = fma2_(K, t & 0x7fffffff7fffffffULL, t);
                accI = fma2_(u, mul2(d, wpk), accI);
            }
            upk2(accI, lo, hi);
            red_add(outr0 + I * 32 + cx, lo);
            red_add(outr1 + I * 32 + cx, hi);
        }
    }
}

extern "C" void kernel_launch(void* const* d_in, const int* in_sizes, int n_in,
                              void* d_out, int out_size) {
    // Identify inputs by element count (robust to ordering):
    // x: 262144, w1: 256, w2: 4, w3: 32640, diff_indices: 8355840 (unused)
    const float* x = nullptr;
    const float* w1 = nullptr;
    const float* w2 = nullptr;
    const float* w3 = nullptr;
    for (int i = 0; i < n_in; i++) {
        switch (in_sizes[i]) {
            case BB * CC:            x  = (const float*)d_in[i]; break;
            case CC:                 w1 = (const float*)d_in[i]; break;
            case 4:                  w2 = (const float*)d_in[i]; break;
            case CC * (CC - 1) / 2:  w3 = (const float*)d_in[i]; break;
            default: break;  // diff_indices not needed
        }
    }

    build_Wrot_kernel<<<(9 * 4 * 1024 + 255) / 256, 256>>>(w3);
    cudaMemsetAsync(d_out, 0, (size_t)out_size * sizeof(float));  // atomics accumulate
    dim3 grid(BB / 16, 9);     // 64 row-groups x 9 rounds = 576 blocks (one wave @ 4/SM)
    son_main_kernel<<<grid, 256>>>(x, w1, w2, (float*)d_out);
}

// round 13
// speedup vs baseline: 1.1599x; 1.0286x over previous
#include <cuda_runtime.h>
#include <cstdint>

#define CC 256
#define BB 1024
typedef unsigned long long ull;

// Round-robin tournament over 8 channel-tiles: rounds 0..6 = perfect matchings
// (every unordered tile-pair exactly once); rounds 7,8 = diagonal tiles.
__constant__ int c_I[9][4] = {
    {7,1,2,3},{7,2,3,4},{7,3,4,5},{7,4,5,6},{7,5,6,0},{7,6,0,1},{7,0,1,2},
    {0,1,2,3},{4,5,6,7}};
__constant__ int c_J[9][4] = {
    {0,6,5,4},{1,0,6,5},{2,1,0,6},{3,2,1,0},{4,3,2,1},{5,4,3,2},{6,5,4,3},
    {0,1,2,3},{4,5,6,7}};

// Pre-ROTATED W tiles: g_Wrot[((rnd*4+k)*1024) + s*32 + cx]
//   = W[J*32 + ((cx+s)&31)][I*32 + cx],  W symmetric from w3, diag 0.
__device__ float g_Wrot[9 * 4 * 1024];

// Builds g_Wrot AND zeroes the output buffer (folded to save a graph node).
__global__ void build_Wrot_kernel(const float* __restrict__ w3, float* __restrict__ out) {
    int idx = blockIdx.x * blockDim.x + threadIdx.x;
    if (idx < BB * CC) out[idx] = 0.0f;          // atomics accumulate into zeroed out
    if (idx >= 9 * 4 * 1024) return;
    int rnd = idx >> 12;
    int rem = idx & 4095;
    int k   = rem >> 10;
    int s   = (rem >> 5) & 31;
    int cx  = rem & 31;
    int I = c_I[rnd][k], J = c_J[rnd][k];
    int c = I * 32 + cx;
    int j = J * 32 + ((cx + s) & 31);
    float v = 0.0f;
    if (j != c) {
        int p = j < c ? j : c;
        int q = j < c ? c : j;
        int e = p * (2 * CC - p - 1) / 2 + (q - p - 1);  // np.triu_indices(CC,1)
        v = w3[e];
    }
    g_Wrot[idx] = v;
}

// ---- packed f32x2 helpers (sm_100a) ----
__device__ __forceinline__ ull pk2(float lo, float hi) {
    ull r;
    asm("mov.b64 %0, {%1, %2};" : "=l"(r) : "f"(lo), "f"(hi));
    return r;
}
__device__ __forceinline__ void upk2(ull v, float& lo, float& hi) {
    asm("mov.b64 {%0, %1}, %2;" : "=f"(lo), "=f"(hi) : "l"(v));
}
__device__ __forceinline__ ull add2(ull a, ull b) {
    ull r;
    asm("add.rn.f32x2 %0, %1, %2;" : "=l"(r) : "l"(a), "l"(b));
    return r;
}
__device__ __forceinline__ ull mul2(ull a, ull b) {
    ull r;
    asm("mul.rn.f32x2 %0, %1, %2;" : "=l"(r) : "l"(a), "l"(b));
    return r;
}
__device__ __forceinline__ ull fma2_(ull a, ull b, ull c) {
    ull r;
    asm("fma.rn.f32x2 %0, %1, %2, %3;" : "=l"(r) : "l"(a), "l"(b), "l"(c));
    return r;
}
__device__ __forceinline__ void red_add(float* p, float v) {
    asm volatile("red.global.add.f32 [%0], %1;" :: "l"(p), "f"(v) : "memory");
}

// v(c,j) = u(|d|)*(x_j-x_c)*W[j,c] is antisymmetric; each unordered pair computed once.
// Row sums -> accI; column sums -> FOUR lane-rotating accumulators (shfl-by-4 every
// 4 steps; acc_r fixed up by a final content-up-by-r shfl). Derivation: contribution
// at step s=4g+r experiences 32-4g downward rotation but needs 32-s -> over-rotated
// by exactly r lanes. W pre-rotated, x duplicated: hot-loop addrs are base+immediate.
__global__ __launch_bounds__(256, 4) void son_main_kernel(
    const float* __restrict__ x, const float* __restrict__ w1,
    const float* __restrict__ w2, float* __restrict__ out)
{
    __shared__ float  Wr[4][1024];     // 16 KB: Wr[k][s*32+cx], pre-rotated
    __shared__ float2 xd[8][8][64];    // 32 KB: xd[p][T][i] = x-pair for ch T*32+(i&31), dup'd

    const int tid  = threadIdx.x;
    const int wrp  = tid >> 5;         // row-pair within group (0..7)
    const int cx   = tid & 31;
    const int rg   = blockIdx.x;       // 0..63
    const int rnd  = blockIdx.y;       // 0..8
    const int rowb = rg * 16;

    // Stage x rows, duplicated within each 32-channel tile (coalesced reads)
    {
        float w1s = w1[tid];
        int T = tid >> 5, ci = tid & 31;
#pragma unroll
        for (int p = 0; p < 8; p++) {
            float lo = x[(rowb + 2 * p) * CC + tid] * w1s;
            float hi = x[(rowb + 2 * p + 1) * CC + tid] * w1s;
            float2 v = make_float2(lo, hi);
            xd[p][T][ci]      = v;
            xd[p][T][ci + 32] = v;
        }
    }
    // Stage the round's 4 rotated W tiles: 1024 float4, linear & coalesced
    {
        const float4* src = reinterpret_cast<const float4*>(g_Wrot + rnd * 4096);
        float4* dst = reinterpret_cast<float4*>(&Wr[0][0]);
#pragma unroll
        for (int m = 0; m < 4; m++)
            dst[tid + m * 256] = __ldg(src + tid + m * 256);
    }
    __syncthreads();

    const float s0 = 0.505f * w2[0], s1 = 0.505f * w2[1];
    const float s2 = 0.505f * w2[2], s3 = 0.505f * w2[3];
    const ull C0 = pk2(s0, s0), C1 = pk2(s1, s1);
    const ull C2 = pk2(s2, s2), C3 = pk2(s3, s3);
    const float kf = 0.495f / 0.505f;
    const ull K = pk2(kf, kf);

    const bool diag = (rnd >= 7);
    float* outr0 = out + (rowb + 2 * wrp) * CC;
    float* outr1 = outr0 + CC;

#pragma unroll 1
    for (int k = 0; k < 4; k++) {
        const int I = c_I[rnd][k], J = c_J[rnd][k];
        const ull nxc = (*reinterpret_cast<const ull*>(&xd[wrp][I][cx])) ^ 0x8000000080000000ULL;
        const ull*   xb = reinterpret_cast<const ull*>(&xd[wrp][J][cx]);  // xb[s]: immediate
        const float* Wb = &Wr[k][cx];                                     // Wb[s*32]: immediate
        float lo, hi;

        if (!diag) {
            ull accI = 0ULL;
            ull accJ[4] = {0ULL, 0ULL, 0ULL, 0ULL};
#pragma unroll
            for (int g = 0; g < 8; g++) {
#pragma unroll
                for (int r = 0; r < 4; r++) {
                    const int s = 4 * g + r;
                    float w = Wb[s * 32];
                    ull xj  = xb[s];
                    ull wpk = pk2(w, w);
                    ull d = add2(xj, nxc);
                    ull a = d & 0x7fffffff7fffffffULL;
                    ull t = fma2_(C3, a, C2);
                    t = fma2_(t, a, C1);
                    t = fma2_(t, a, C0);
                    ull u = fma2_(K, t & 0x7fffffff7fffffffULL, t);
                    ull m = mul2(d, wpk);
                    accI    = fma2_(u, m, accI);
                    accJ[r] = fma2_(u, m, accJ[r]);
                }
                // rotate all four column accumulators down by 4
#pragma unroll
                for (int r = 0; r < 4; r++)
                    accJ[r] = __shfl_sync(0xffffffffu, accJ[r], (cx + 4) & 31);
            }
            // fix-ups: acc_r over-rotated by r -> move content up by r
            accJ[1] = __shfl_sync(0xffffffffu, accJ[1], (cx + 31) & 31);
            accJ[2] = __shfl_sync(0xffffffffu, accJ[2], (cx + 30) & 31);
            accJ[3] = __shfl_sync(0xffffffffu, accJ[3], (cx + 29) & 31);

            upk2(accI, lo, hi);
            red_add(outr0 + I * 32 + cx, lo);
            red_add(outr1 + I * 32 + cx, hi);
            ull negJ = add2(add2(accJ[0], accJ[1]), add2(accJ[2], accJ[3]))
                       ^ 0x8000000080000000ULL;                       // v(j,c) = -v(c,j)
            upk2(negJ, lo, hi);
            red_add(outr0 + J * 32 + cx, lo);
            red_add(outr1 + J * 32 + cx, hi);
        } else {
            ull accI = 0ULL;
#pragma unroll
            for (int s = 0; s < 32; s++) {
                float w = Wb[s * 32];
                ull xj  = xb[s];
                ull wpk = pk2(w, w);
                ull d = add2(xj, nxc);
                ull a = d & 0x7fffffff7fffffffULL;
                ull t = fma2_(C3, a, C2);
                t = fma2_(t, a, C1);
                t = fma2_(t, a, C0);
                ull u = fma2_(K, t & 0x7fffffff7fffffffULL, t);
                accI = fma2_(u, mul2(d, wpk), accI);
            }
            upk2(accI, lo, hi);
            red_add(outr0 + I * 32 + cx, lo);
            red_add(outr1 + I * 32 + cx, hi);
        }
    }
}

extern "C" void kernel_launch(void* const* d_in, const int* in_sizes, int n_in,
                              void* d_out, int out_size) {
    // Identify inputs by element count (robust to ordering):
    // x: 262144, w1: 256, w2: 4, w3: 32640, diff_indices: 8355840 (unused)
    const float* x = nullptr;
    const float* w1 = nullptr;
    const float* w2 = nullptr;
    const float* w3 = nullptr;
    for (int i = 0; i < n_in; i++) {
        switch (in_sizes[i]) {
            case BB * CC:            x  = (const float*)d_in[i]; break;
            case CC:                 w1 = (const float*)d_in[i]; break;
            case 4:                  w2 = (const float*)d_in[i]; break;
            case CC * (CC - 1) / 2:  w3 = (const float*)d_in[i]; break;
            default: break;  // diff_indices not needed
        }
    }

    // One kernel builds g_Wrot and zeroes out (grid sized for the larger job).
    build_Wrot_kernel<<<(BB * CC + 255) / 256, 256>>>(w3, (float*)d_out);
    dim3 grid(BB / 16, 9);     // 64 row-groups x 9 rounds = 576 blocks (one wave @ 4/SM)
    son_main_kernel<<<grid, 256>>>(x, w1, w2, (float*)d_out);
}